// round 16
// baseline (speedup 1.0000x reference)
#include <cuda_runtime.h>
#include <math.h>

#define BATCH 4
#define NPTS  8192
#define RT 128                      // rows per block
#define CSPLIT 4
#define CPB (NPTS / CSPLIT)         // 2048 cols per block
#define CHUNK 256                   // cols staged per chunk
#define NCH (CPB / CHUNK)           // 8 chunks
#define THREADS 256
#define RCH (NPTS / RT)             // 64 row groups per batch
#define NGROUPS (BATCH * RCH + BATCH * CSPLIT)   // 256 + 16 = 272
#define MST 257                     // padded smem row stride (floats)

__device__ unsigned g_rmax[BATCH * NPTS];   // pred  -> label
__device__ unsigned g_cmax[BATCH * NPTS];   // label -> pred
__device__ unsigned g_rcnt[BATCH * RCH];    // row-group completion counters
__device__ unsigned g_ccnt[BATCH * CSPLIT]; // col-group completion counters
__device__ unsigned g_groups = 0;           // harvested-group counter
__device__ float    g_sum = 0.0f;           // global sqrt-sum accumulator

__device__ __forceinline__ unsigned enc(float f) {
    unsigned u = __float_as_uint(f);
    return u ^ ((unsigned)((int)u >> 31) | 0x80000000u);
}
__device__ __forceinline__ float dec(unsigned k) {
    unsigned u = (k & 0x80000000u) ? (k ^ 0x80000000u) : ~k;
    return __uint_as_float(u);
}

// Harvest a finalized group of n per-point maxes: sqrt, block-reduce,
// one float atomicAdd into g_sum, and reset slots for the next replay.
// __noinline__ keeps this code out of the hot loop's register allocation.
__device__ __noinline__ void harvest_group(unsigned* __restrict__ g,
                                           int base, int n, int tid) {
    __shared__ float hs[THREADS / 32];
    float s = 0.0f;
    for (int i = tid; i < n; i += THREADS) {
        const unsigned k = g[base + i];
        g[base + i] = 0u;                       // reset for next replay
        s += sqrtf(fmaxf(-2.0f * dec(k), 0.0f));
    }
    #pragma unroll
    for (int off = 16; off > 0; off >>= 1)
        s += __shfl_down_sync(0xFFFFFFFFu, s, off);
    if ((tid & 31) == 0) hs[tid >> 5] = s;
    __syncthreads();
    if (tid == 0) {
        float bs = 0.0f;
        #pragma unroll
        for (int w = 0; w < THREADS / 32; w++) bs += hs[w];
        atomicAdd(&g_sum, bs);
    }
    __syncthreads();                            // hs reuse safety across calls
}

// One block: 128 pred rows x 2048 label cols (8 prefetched 256-col chunks).
// Per entry u = x.y - x^2/2 - y^2/2 = -d^2/2; BOTH direction maxes use u.
// Blocks that CLOSE a row/col group harvest it inline; the block closing the
// last of the 272 groups writes the scalar and resets all replay state.
__global__ __launch_bounds__(THREADS, 3)
void chamfer_main(const float* __restrict__ pred,
                  const float* __restrict__ label,
                  float* __restrict__ out) {
    const int b      = blockIdx.z;
    const int rbase  = blockIdx.x * RT;
    const int cb     = blockIdx.y * CPB;
    const float* __restrict__ A  = pred  + (size_t)b * NPTS * 3;
    const float* __restrict__ Bp = label + (size_t)b * NPTS * 3;

    __shared__ float4 sB[CHUNK];        // (bx, by, bz, nwy) per col, 4 KB
    __shared__ float  sM[16 * MST];     // merge transpose buffer, ~16 KB

    const int tid = threadIdx.x;
    const int rg  = tid >> 4;
    const int cg  = tid & 15;

    // ---- Prologue: this thread's 8 A rows (96 contiguous bytes) ----
    float ax[8], ay[8], az[8], nwx[8], rowm[8];
    {
        const int r0 = rbase + rg * 8;                  // 16B-aligned start
        const float4* Ar = (const float4*)(A + (size_t)r0 * 3);
        float av[24];
        #pragma unroll
        for (int i = 0; i < 6; i++) *(float4*)&av[4 * i] = Ar[i];
        #pragma unroll
        for (int r = 0; r < 8; r++) {
            ax[r] = av[3 * r + 0];
            ay[r] = av[3 * r + 1];
            az[r] = av[3 * r + 2];
            nwx[r] = -0.5f * fmaf(ax[r], ax[r], fmaf(ay[r], ay[r], az[r] * az[r]));
            rowm[r] = -3.0e38f;
        }
    }

    // Preload chunk 0's column for this thread.
    float nbx, nby, nbz;
    {
        const float* p = Bp + (size_t)(cb + tid) * 3;
        nbx = p[0]; nby = p[1]; nbz = p[2];
    }

    for (int ch = 0; ch < NCH; ch++) {
        __syncthreads();                                // sB free, prev sM reads done
        {
            const float bx = nbx, by = nby, bz = nbz;
            const float nwy = -0.5f * fmaf(bx, bx, fmaf(by, by, bz * bz));
            sB[tid] = make_float4(bx, by, bz, nwy);
        }
        __syncthreads();

        // Prefetch next chunk's column (hidden under compute).
        if (ch + 1 < NCH) {
            const float* p = Bp + (size_t)(cb + (ch + 1) * CHUNK + tid) * 3;
            nbx = p[0]; nby = p[1]; nbz = p[2];
        }

        float colm[16];
        #pragma unroll
        for (int k = 0; k < 16; k++) colm[k] = -3.0e38f;

        // Main compute: 16 cols x 8 rows, scalar FFMA, maxes in regs.
        #pragma unroll
        for (int cc = 0; cc < 16; cc++) {
            const float4 v = sB[cc * 16 + cg];          // lanes -> consecutive float4s
            float cm = colm[cc];
            #pragma unroll
            for (int r = 0; r < 8; r++) {
                float t = fmaf(az[r], v.z, v.w);        // az*bz - y^2/2
                t = fmaf(ay[r], v.y, t);                // + ay*by
                t = fmaf(ax[r], v.x, t);                // + ax*bx
                t += nwx[r];                            // - x^2/2  => -d^2/2
                rowm[r] = fmaxf(rowm[r], t);
                cm = fmaxf(cm, t);
            }
            colm[cc] = cm;
        }

        // Col merge for this chunk: 16 rg writers per col through sM.
        #pragma unroll
        for (int cc = 0; cc < 16; cc++)
            sM[rg * MST + cc * 16 + cg] = colm[cc];
        __syncthreads();
        {
            float m = sM[tid];                          // col = tid of this chunk
            #pragma unroll
            for (int g = 1; g < 16; g++) m = fmaxf(m, sM[g * MST + tid]);
            atomicMax(&g_cmax[(size_t)b * NPTS + cb + ch * CHUNK + tid], enc(m));
        }
    }

    // ---- Row merge: transpose through smem, one RED per row ----
    __syncthreads();
    #pragma unroll
    for (int r = 0; r < 8; r++)
        sM[cg * MST + rg * 8 + r] = rowm[r];
    __syncthreads();
    if (tid < RT) {
        float m = sM[tid];
        #pragma unroll
        for (int g = 1; g < 16; g++) m = fmaxf(m, sM[g * MST + tid]);
        atomicMax(&g_rmax[(size_t)b * NPTS + rbase + tid], enc(m));
    }

    // ---- Group-completion accounting (release: fence before inc) ----
    __threadfence();
    __syncthreads();
    __shared__ int s_doRow, s_doCol;
    if (tid == 0) {
        s_doRow = (atomicAdd(&g_rcnt[b * RCH + blockIdx.x], 1u) == CSPLIT - 1);
        s_doCol = (atomicAdd(&g_ccnt[b * CSPLIT + blockIdx.y], 1u) == RCH - 1);
    }
    __syncthreads();

    int nharv = 0;
    if (s_doRow | s_doCol) __threadfence();             // acquire
    if (s_doRow) { harvest_group(g_rmax, b * NPTS + rbase, RT,  tid); nharv++; }
    if (s_doCol) { harvest_group(g_cmax, b * NPTS + cb,    CPB, tid); nharv++; }

    if (nharv && tid == 0) {
        if (s_doRow) g_rcnt[b * RCH + blockIdx.x]   = 0u;   // reset for replay
        if (s_doCol) g_ccnt[b * CSPLIT + blockIdx.y] = 0u;
        __threadfence();                                // release g_sum add
        const unsigned done = atomicAdd(&g_groups, (unsigned)nharv) + (unsigned)nharv;
        if (done == (unsigned)NGROUPS) {
            __threadfence();                            // acquire all g_sum adds
            out[0] = g_sum * (1.0f / (float)(BATCH * NPTS));
            g_sum = 0.0f;                               // reset for next replay
            g_groups = 0u;
        }
    }
}

extern "C" void kernel_launch(void* const* d_in, const int* in_sizes, int n_in,
                              void* d_out, int out_size) {
    const float* pred  = (const float*)d_in[0];
    const float* label = (const float*)d_in[1];
    float* out = (float*)d_out;

    dim3 grid(NPTS / RT, CSPLIT, BATCH);   // 64 x 4 x 4 = 1024 blocks
    chamfer_main<<<grid, THREADS>>>(pred, label, out);
}